// round 12
// baseline (speedup 1.0000x reference)
#include <cuda_runtime.h>
#include <cuda_fp16.h>
#include <string.h>

// GooLayer: B=2, M=64, D=64, T=8192 — chunked linear-scan, 3 kernels:
//  K1: pass A — stores g' = (f+ki*h)*karg as fp16 (1-way noise-shaped
//      rounding); stages ONLY g' (computed at load time) through smem;
//      emits chunk finals AND mid-chunk states.
//  K2: combine — inline homogeneous M^256/M^512 + matvecs -> 32 sub-chunk ICs
//  K3: pass B — one warp per (bm, subchunk=256 steps), all 64 d (2 chains/lane)

#define BBX 2
#define MMX 64
#define DDX 64
#define TTX 8192
#define DAMP 0.9998f
#define NCH 16
#define CL (TTX / NCH)                  // 512
#define NW8 (CL / 8)                    // 64 fp16-octet windows per chunk
#define K1NT (CL / 32)                  // 16 staging tiles per chunk
#define NSC 32                          // sub-chunks (256 steps) for K3
#define FQ (TTX / 4)                    // float4 per chain (2048)
#define L2E2 2.8853900817779268f        // 2*log2(e)

// g scratch: [bm][chunk][w8][d] -> uint4 (8 fp16, t-ascending), coalesced in d
__device__ uint4 g_scr[(size_t)BBX * MMX * NCH * NW8 * DDX];
__device__ float g_fin[BBX * MMX * NCH * DDX * 2];
__device__ float g_mid[BBX * MMX * NCH * DDX * 2];
__device__ float g_ic [BBX * MMX * NSC * DDX * 2];

__device__ __forceinline__ float ex2_fast(float x) {
    float y; asm("ex2.approx.f32 %0, %1;" : "=f"(y) : "f"(x)); return y;
}
__device__ __forceinline__ float rcp_fast(float x) {
    float y; asm("rcp.approx.f32 %0, %1;" : "=f"(y) : "f"(x)); return y;
}
__device__ __forceinline__ __half2 u32_as_half2(unsigned u) {
    __half2 h; memcpy(&h, &u, 4); return h;
}
__device__ __forceinline__ unsigned half2_as_u32(__half2 h) {
    unsigned u; memcpy(&u, &h, 4); return u;
}

// ---------------- K1: pass A ----------------
// 128 threads = 4 warps; one warp per (bm, chunk, half) unit. 1024 blocks.
__global__ __launch_bounds__(128)
void k1_passA(const float* __restrict__ forces, const float* __restrict__ home,
              const float* __restrict__ masses, const float* __restrict__ tensions,
              const float* __restrict__ gains)
{
    __shared__ float gt[4][32][36];   // staged g' tiles: [warp][chain][t]
    __shared__ float kis[4][32];      // per-chain ki (unscaled)

    const int tid = threadIdx.x, wid = tid >> 5, lane = tid & 31;
    const int unit  = blockIdx.x * 4 + wid;        // 0..4095
    const int bm    = unit >> 5;
    const int chunk = (unit >> 1) & 15;
    const int half  = unit & 1;
    const int m = bm & 63;
    const int d = half * 32 + lane;

    const float ki   = tensions[m * 64 + d] / masses[m];
    const float nki  = -ki;
    const float karg = gains[m] * (DAMP * L2E2);   // state scale (per m)

    kis[wid][lane] = ki;
    __syncwarp();

    // per LDG.128: lanes cover 4 chains x 8 float4 (full 128B lines)
    const int lch4 = lane >> 3;                    // 0..3
    const int lt8  = lane & 7;                     // 0..7
    const size_t wb = ((size_t)(bm * 64 + half * 32)) * TTX + (size_t)chunk * CL;
    const float4* __restrict__ fbase = (const float4*)(forces + wb) + lt8;
    const float4* __restrict__ hbase = (const float4*)(home  + wb) + lt8;

    // ki for the chains this lane stages (constant over tiles)
    float kk0 = kis[wid][ 0 + lch4], kk1 = kis[wid][ 4 + lch4];
    float kk2 = kis[wid][ 8 + lch4], kk3 = kis[wid][12 + lch4];
    float kk4 = kis[wid][16 + lch4], kk5 = kis[wid][20 + lch4];
    float kk6 = kis[wid][24 + lch4], kk7 = kis[wid][28 + lch4];

    uint4* gw = g_scr + ((size_t)(bm * NCH + chunk) * NW8) * 64 + d;

    float pos = 0.f, vs = 0.f, e = 0.f;            // karg-scaled state

    float4 nf0, nf1, nf2, nf3, nf4, nf5, nf6, nf7;
    float4 nh0, nh1, nh2, nh3, nh4, nh5, nh6, nh7;

#define K1_LDALL(OFF)                                                          \
    nf0 = __ldcs(fbase + (size_t)(0 * 4 + lch4) * FQ + (OFF));                 \
    nf1 = __ldcs(fbase + (size_t)(1 * 4 + lch4) * FQ + (OFF));                 \
    nf2 = __ldcs(fbase + (size_t)(2 * 4 + lch4) * FQ + (OFF));                 \
    nf3 = __ldcs(fbase + (size_t)(3 * 4 + lch4) * FQ + (OFF));                 \
    nf4 = __ldcs(fbase + (size_t)(4 * 4 + lch4) * FQ + (OFF));                 \
    nf5 = __ldcs(fbase + (size_t)(5 * 4 + lch4) * FQ + (OFF));                 \
    nf6 = __ldcs(fbase + (size_t)(6 * 4 + lch4) * FQ + (OFF));                 \
    nf7 = __ldcs(fbase + (size_t)(7 * 4 + lch4) * FQ + (OFF));                 \
    nh0 = __ldcs(hbase + (size_t)(0 * 4 + lch4) * FQ + (OFF));                 \
    nh1 = __ldcs(hbase + (size_t)(1 * 4 + lch4) * FQ + (OFF));                 \
    nh2 = __ldcs(hbase + (size_t)(2 * 4 + lch4) * FQ + (OFF));                 \
    nh3 = __ldcs(hbase + (size_t)(3 * 4 + lch4) * FQ + (OFF));                 \
    nh4 = __ldcs(hbase + (size_t)(4 * 4 + lch4) * FQ + (OFF));                 \
    nh5 = __ldcs(hbase + (size_t)(5 * 4 + lch4) * FQ + (OFF));                 \
    nh6 = __ldcs(hbase + (size_t)(6 * 4 + lch4) * FQ + (OFF));                 \
    nh7 = __ldcs(hbase + (size_t)(7 * 4 + lch4) * FQ + (OFF));

    // g' = (f + ki*h) * karg, per element
#define K1_G4(NF, NH, KK)                                                      \
    make_float4(fmaf(KK, NH.x, NF.x) * karg, fmaf(KK, NH.y, NF.y) * karg,      \
                fmaf(KK, NH.z, NF.z) * karg, fmaf(KK, NH.w, NF.w) * karg)

    K1_LDALL(0)

    for (int tile = 0; tile < K1NT; tile++) {
        float4 ng0 = K1_G4(nf0, nh0, kk0), ng1 = K1_G4(nf1, nh1, kk1);
        float4 ng2 = K1_G4(nf2, nh2, kk2), ng3 = K1_G4(nf3, nh3, kk3);
        float4 ng4 = K1_G4(nf4, nh4, kk4), ng5 = K1_G4(nf5, nh5, kk5);
        float4 ng6 = K1_G4(nf6, nh6, kk6), ng7 = K1_G4(nf7, nh7, kk7);

        __syncwarp();
        *(float4*)&gt[wid][ 0 + lch4][lt8 * 4] = ng0;
        *(float4*)&gt[wid][ 4 + lch4][lt8 * 4] = ng1;
        *(float4*)&gt[wid][ 8 + lch4][lt8 * 4] = ng2;
        *(float4*)&gt[wid][12 + lch4][lt8 * 4] = ng3;
        *(float4*)&gt[wid][16 + lch4][lt8 * 4] = ng4;
        *(float4*)&gt[wid][20 + lch4][lt8 * 4] = ng5;
        *(float4*)&gt[wid][24 + lch4][lt8 * 4] = ng6;
        *(float4*)&gt[wid][28 + lch4][lt8 * 4] = ng7;
        __syncwarp();

        if (tile + 1 < K1NT) { K1_LDALL((tile + 1) * 8) }

        // 32 steps for chain = lane; quantize with 1-way error feedback
        unsigned uq0 = 0, uq1 = 0;
        #pragma unroll
        for (int j = 0; j < 8; j++) {
            float4 gv = *(const float4*)&gt[wid][lane][4 * j];
            __half q0, q1, q2, q3;
            float t, r, acc;

            t = gv.x + e; q0 = __float2half_rn(t); r = __half2float(q0); e = t - r;
            acc = fmaf(nki, pos, r); vs = fmaf(vs, DAMP, acc); pos = fmaf(vs, DAMP, pos);
            t = gv.y + e; q1 = __float2half_rn(t); r = __half2float(q1); e = t - r;
            acc = fmaf(nki, pos, r); vs = fmaf(vs, DAMP, acc); pos = fmaf(vs, DAMP, pos);
            t = gv.z + e; q2 = __float2half_rn(t); r = __half2float(q2); e = t - r;
            acc = fmaf(nki, pos, r); vs = fmaf(vs, DAMP, acc); pos = fmaf(vs, DAMP, pos);
            t = gv.w + e; q3 = __float2half_rn(t); r = __half2float(q3); e = t - r;
            acc = fmaf(nki, pos, r); vs = fmaf(vs, DAMP, acc); pos = fmaf(vs, DAMP, pos);

            unsigned ua = half2_as_u32(__halves2half2(q0, q1));  // q0 low
            unsigned ub = half2_as_u32(__halves2half2(q2, q3));
            if ((j & 1) == 0) { uq0 = ua; uq1 = ub; }
            else {
                uint4 pk; pk.x = uq0; pk.y = uq1; pk.z = ua; pk.w = ub;
                __stcs(gw + (size_t)(tile * 4 + (j >> 1)) * 64, pk);
            }
        }

        if (tile == K1NT / 2 - 1) {   // state after 256 steps
            float* mid = g_mid + ((size_t)(bm * NCH + chunk) * 64 + d) * 2;
            mid[0] = pos; mid[1] = vs;
        }
    }
#undef K1_LDALL
#undef K1_G4

    float* fin = g_fin + ((size_t)(bm * NCH + chunk) * 64 + d) * 2;
    fin[0] = pos; fin[1] = vs;
}

// ---------------- K2: combine (homogeneous + 32 sub-chunk ICs) ----------------
__global__ __launch_bounds__(256)
void k2_combine(const float* __restrict__ masses, const float* __restrict__ tensions)
{
    int idx = blockIdx.x * 256 + threadIdx.x;      // bm*64+d
    int bm = idx >> 6, d = idx & 63, m = bm & 63;
    const float nki = -(tensions[m * 64 + d] / masses[m]);

    // homogeneous columns at 256 and 512 steps
    float p1 = 1.f, v1 = 0.f, p2 = 0.f, v2 = 1.f;
    #pragma unroll 8
    for (int t = 0; t < CL / 2; t++) {
        v1 = fmaf(v1, DAMP, nki * p1); p1 = fmaf(v1, DAMP, p1);
        v2 = fmaf(v2, DAMP, nki * p2); p2 = fmaf(v2, DAMP, p2);
    }
    const float q1 = p1, w1 = v1, q2 = p2, w2 = v2;   // M^256
    #pragma unroll 8
    for (int t = 0; t < CL / 2; t++) {
        v1 = fmaf(v1, DAMP, nki * p1); p1 = fmaf(v1, DAMP, p1);
        v2 = fmaf(v2, DAMP, nki * p2); p2 = fmaf(v2, DAMP, p2);
    }                                                  // M^512

    float pos = 0.f, vs = 0.f;
    #pragma unroll
    for (int c = 0; c < NCH; c++) {
        size_t oi = ((size_t)(bm * NSC + 2 * c) * 64 + d) * 2;     // sub-chunk 2c
        g_ic[oi] = pos; g_ic[oi + 1] = vs;
        size_t om = ((size_t)(bm * NCH + c) * 64 + d) * 2;
        float mp = fmaf(q1, pos, fmaf(q2, vs, g_mid[om]));
        float mv = fmaf(w1, pos, fmaf(w2, vs, g_mid[om + 1]));
        size_t oj = ((size_t)(bm * NSC + 2 * c + 1) * 64 + d) * 2; // sub-chunk 2c+1
        g_ic[oj] = mp; g_ic[oj + 1] = mv;
        float np = fmaf(p1, pos, fmaf(p2, vs, g_fin[om]));
        float nv = fmaf(v1, pos, fmaf(v2, vs, g_fin[om + 1]));
        pos = np; vs = nv;
    }
}

// ---------------- K3: pass B — one warp per (bm, subchunk), 2 chains/lane ----
__global__ __launch_bounds__(256)
void k3_passB(const float* __restrict__ mic, const float* __restrict__ masses,
              const float* __restrict__ tensions, float* __restrict__ out)
{
    __shared__ float tile_s[8][16][36];

    const int tid = threadIdx.x, wid = tid >> 5, lane = tid & 31;
    const int unit = blockIdx.x * 8 + wid;         // 0..4095
    const int bm   = unit >> 5;
    const int sc   = unit & 31;                    // sub-chunk (256 steps)
    const int chunk = sc >> 1;
    const int m = bm & 63;
    const int d0 = lane, d1 = lane + 32;

    const float inv_mass = 1.f / masses[m];
    const float nki0 = -(tensions[m * 64 + d0] * inv_mass);
    const float nki1 = -(tensions[m * 64 + d1] * inv_mass);
    const float micv0 = mic[bm * 64 + d0];
    const float micv1 = mic[bm * 64 + d1];
    const float m2mic0 = -2.f * micv0;
    const float m2mic1 = -2.f * micv1;
    const float micsum = micv0 + micv1;

    const uint4* gw0 = g_scr + ((size_t)((bm * NCH + chunk) * NW8)
                                + (size_t)(sc & 1) * (NW8 / 2)) * 64 + d0;
    const uint4* gw1 = gw0 + 32;
    const size_t ib = ((size_t)(bm * NSC + sc) * 64) * 2;
    float pos0 = g_ic[ib + 2 * d0], vs0 = g_ic[ib + 2 * d0 + 1];
    float pos1 = g_ic[ib + 2 * d1], vs1 = g_ic[ib + 2 * d1 + 1];
    float* obase = out + (size_t)bm * TTX + (size_t)sc * (CL / 2);
    float (*tile)[36] = tile_s[wid];

    uint4 ca00, ca01, ca10, ca11, cb00, cb01, cb10, cb11;
    ca00 = __ldcs(gw0 + 0);  ca01 = __ldcs(gw0 + 64);
    ca10 = __ldcs(gw1 + 0);  ca11 = __ldcs(gw1 + 64);

    const int NWND = (CL / 2) / 16;                // 16 windows of 16 steps

#define K3_QQ(G0, G1, R)                                                       \
    _Pragma("unroll")                                                          \
    for (int i = 0; i < 4; i++) {                                              \
        float2 fa = __half22float2(u32_as_half2((&G0.x)[i]));                  \
        float2 fb = __half22float2(u32_as_half2((&G1.x)[i]));                  \
        _Pragma("unroll")                                                      \
        for (int s = 0; s < 2; s++) {                                          \
            float gv0 = s ? fa.y : fa.x;                                       \
            float gv1 = s ? fb.y : fb.x;                                       \
            float a0 = fmaf(nki0, pos0, gv0);                                  \
            vs0  = fmaf(vs0, DAMP, a0);                                        \
            pos0 = fmaf(vs0, DAMP, pos0);                                      \
            float a1 = fmaf(nki1, pos1, gv1);                                  \
            vs1  = fmaf(vs1, DAMP, a1);                                        \
            pos1 = fmaf(vs1, DAMP, pos1);                                      \
            float r0 = rcp_fast(ex2_fast(vs0) + 1.f);                          \
            float r1 = rcp_fast(ex2_fast(vs1) + 1.f);                          \
            tile[(R) + i * 2 + s][lane] =                                      \
                fmaf(r0, m2mic0, fmaf(r1, m2mic1, micsum));                    \
        }                                                                      \
    }

#define K3W(W, C00, C01, C10, C11, N00, N01, N10, N11)                         \
    {                                                                          \
        const int w_ = (W);                                                    \
        if (w_ + 1 < NWND) {                                                   \
            N00 = __ldcs(gw0 + (size_t)(2 * (w_ + 1) + 0) * 64);               \
            N01 = __ldcs(gw0 + (size_t)(2 * (w_ + 1) + 1) * 64);               \
            N10 = __ldcs(gw1 + (size_t)(2 * (w_ + 1) + 0) * 64);               \
            N11 = __ldcs(gw1 + (size_t)(2 * (w_ + 1) + 1) * 64);               \
        }                                                                      \
        K3_QQ(C00, C10, 0)                                                     \
        K3_QQ(C01, C11, 8)                                                     \
        __syncwarp();                                                          \
        const int row = lane & 15, cb = (lane >> 4) * 16;                      \
        float s0 = 0.f, s1 = 0.f, s2 = 0.f, s3 = 0.f;                          \
        _Pragma("unroll")                                                      \
        for (int i = 0; i < 4; i++) {                                          \
            float4 v = *(const float4*)&tile[row][cb + 4 * i];                 \
            s0 += v.x; s1 += v.y; s2 += v.z; s3 += v.w;                        \
        }                                                                      \
        float sum = (s0 + s1) + (s2 + s3);                                     \
        sum += __shfl_down_sync(0xffffffffu, sum, 16);                         \
        if (lane < 16) obase[w_ * 16 + lane] = sum;                            \
        __syncwarp();                                                          \
    }

    for (int w = 0; w < NWND; w += 2) {
        K3W(w,     ca00, ca01, ca10, ca11, cb00, cb01, cb10, cb11)
        K3W(w + 1, cb00, cb01, cb10, cb11, ca00, ca01, ca10, ca11)
    }
#undef K3W
#undef K3_QQ
}

extern "C" void kernel_launch(void* const* d_in, const int* in_sizes, int n_in,
                              void* d_out, int out_size)
{
    const float* forces   = (const float*)d_in[0];
    const float* home     = (const float*)d_in[1];
    const float* mic      = (const float*)d_in[2];
    const float* masses   = (const float*)d_in[3];
    const float* tensions = (const float*)d_in[4];
    const float* gains    = (const float*)d_in[5];

    k1_passA  <<<1024, 128>>>(forces, home, masses, tensions, gains);
    k2_combine<<<32,   256>>>(masses, tensions);
    k3_passB  <<<512,  256>>>(mic, masses, tensions, (float*)d_out);
}

// round 13
// speedup vs baseline: 1.1402x; 1.1402x over previous
#include <cuda_runtime.h>
#include <cuda_fp16.h>
#include <string.h>

// GooLayer: B=2, M=64, D=64, T=8192 — chunked linear-scan, 3 kernels:
//  K1: pass A — stores g' = (f+ki*h)*(gain*DAMP) as fp16 (1-way noise-shaped
//      rounding); stages only g' (computed at load) through smem; chunk finals.
//  K2: combine — inline homogeneous M^512 + 16 2x2 matvecs -> chunk ICs
//  K3: pass B — one warp per (bm,chunk), all 64 d (2 chains/lane);
//      tanh via MUFU.TANH directly on the scaled state.

#define BBX 2
#define MMX 64
#define DDX 64
#define TTX 8192
#define DAMP 0.9998f
#define NCH 16
#define CL (TTX / NCH)                  // 512
#define NW8 (CL / 8)                    // 64 fp16-octet windows per chunk
#define K1NT (CL / 32)                  // 16 staging tiles per chunk
#define FQ (TTX / 4)                    // float4 per chain (2048)

// g scratch: [bm][chunk][w8][d] -> uint4 (8 fp16, t-ascending), coalesced in d
__device__ uint4 g_scr[(size_t)BBX * MMX * NCH * NW8 * DDX];
__device__ float g_fin[BBX * MMX * NCH * DDX * 2];
__device__ float g_ic [BBX * MMX * NCH * DDX * 2];

__device__ __forceinline__ float tanh_fast(float x) {
    float y; asm("tanh.approx.f32 %0, %1;" : "=f"(y) : "f"(x)); return y;
}
__device__ __forceinline__ __half2 u32_as_half2(unsigned u) {
    __half2 h; memcpy(&h, &u, 4); return h;
}
__device__ __forceinline__ unsigned half2_as_u32(__half2 h) {
    unsigned u; memcpy(&u, &h, 4); return u;
}

// ---------------- K1: pass A ----------------
// 128 threads = 4 warps; one warp per (bm, chunk, half) unit. 1024 blocks.
__global__ __launch_bounds__(128)
void k1_passA(const float* __restrict__ forces, const float* __restrict__ home,
              const float* __restrict__ masses, const float* __restrict__ tensions,
              const float* __restrict__ gains)
{
    __shared__ float gt[4][32][36];   // staged g' tiles: [warp][chain][t]
    __shared__ float kis[4][32];      // per-chain ki

    const int tid = threadIdx.x, wid = tid >> 5, lane = tid & 31;
    const int unit  = blockIdx.x * 4 + wid;        // 0..4095
    const int bm    = unit >> 5;
    const int chunk = (unit >> 1) & 15;
    const int half  = unit & 1;
    const int m = bm & 63;
    const int d = half * 32 + lane;

    const float ki   = tensions[m * 64 + d] / masses[m];
    const float nki  = -ki;
    const float karg = gains[m] * DAMP;            // state scale (tanh arg)

    kis[wid][lane] = ki;
    __syncwarp();

    // per LDG.128: lanes cover 4 chains x 8 float4 (full 128B lines)
    const int lch4 = lane >> 3;                    // 0..3
    const int lt8  = lane & 7;                     // 0..7
    const size_t wb = ((size_t)(bm * 64 + half * 32)) * TTX + (size_t)chunk * CL;
    const float4* __restrict__ fbase = (const float4*)(forces + wb) + lt8;
    const float4* __restrict__ hbase = (const float4*)(home  + wb) + lt8;

    float kk0 = kis[wid][ 0 + lch4], kk1 = kis[wid][ 4 + lch4];
    float kk2 = kis[wid][ 8 + lch4], kk3 = kis[wid][12 + lch4];
    float kk4 = kis[wid][16 + lch4], kk5 = kis[wid][20 + lch4];
    float kk6 = kis[wid][24 + lch4], kk7 = kis[wid][28 + lch4];

    uint4* gw = g_scr + ((size_t)(bm * NCH + chunk) * NW8) * 64 + d;

    float pos = 0.f, vs = 0.f, e = 0.f;            // karg-scaled state

    float4 nf0, nf1, nf2, nf3, nf4, nf5, nf6, nf7;
    float4 nh0, nh1, nh2, nh3, nh4, nh5, nh6, nh7;

#define K1_LDALL(OFF)                                                          \
    nf0 = __ldcs(fbase + (size_t)(0 * 4 + lch4) * FQ + (OFF));                 \
    nf1 = __ldcs(fbase + (size_t)(1 * 4 + lch4) * FQ + (OFF));                 \
    nf2 = __ldcs(fbase + (size_t)(2 * 4 + lch4) * FQ + (OFF));                 \
    nf3 = __ldcs(fbase + (size_t)(3 * 4 + lch4) * FQ + (OFF));                 \
    nf4 = __ldcs(fbase + (size_t)(4 * 4 + lch4) * FQ + (OFF));                 \
    nf5 = __ldcs(fbase + (size_t)(5 * 4 + lch4) * FQ + (OFF));                 \
    nf6 = __ldcs(fbase + (size_t)(6 * 4 + lch4) * FQ + (OFF));                 \
    nf7 = __ldcs(fbase + (size_t)(7 * 4 + lch4) * FQ + (OFF));                 \
    nh0 = __ldcs(hbase + (size_t)(0 * 4 + lch4) * FQ + (OFF));                 \
    nh1 = __ldcs(hbase + (size_t)(1 * 4 + lch4) * FQ + (OFF));                 \
    nh2 = __ldcs(hbase + (size_t)(2 * 4 + lch4) * FQ + (OFF));                 \
    nh3 = __ldcs(hbase + (size_t)(3 * 4 + lch4) * FQ + (OFF));                 \
    nh4 = __ldcs(hbase + (size_t)(4 * 4 + lch4) * FQ + (OFF));                 \
    nh5 = __ldcs(hbase + (size_t)(5 * 4 + lch4) * FQ + (OFF));                 \
    nh6 = __ldcs(hbase + (size_t)(6 * 4 + lch4) * FQ + (OFF));                 \
    nh7 = __ldcs(hbase + (size_t)(7 * 4 + lch4) * FQ + (OFF));

#define K1_G4(NF, NH, KK)                                                      \
    make_float4(fmaf(KK, NH.x, NF.x) * karg, fmaf(KK, NH.y, NF.y) * karg,      \
                fmaf(KK, NH.z, NF.z) * karg, fmaf(KK, NH.w, NF.w) * karg)

    K1_LDALL(0)

    for (int tile = 0; tile < K1NT; tile++) {
        float4 ng0 = K1_G4(nf0, nh0, kk0), ng1 = K1_G4(nf1, nh1, kk1);
        float4 ng2 = K1_G4(nf2, nh2, kk2), ng3 = K1_G4(nf3, nh3, kk3);
        float4 ng4 = K1_G4(nf4, nh4, kk4), ng5 = K1_G4(nf5, nh5, kk5);
        float4 ng6 = K1_G4(nf6, nh6, kk6), ng7 = K1_G4(nf7, nh7, kk7);

        __syncwarp();
        *(float4*)&gt[wid][ 0 + lch4][lt8 * 4] = ng0;
        *(float4*)&gt[wid][ 4 + lch4][lt8 * 4] = ng1;
        *(float4*)&gt[wid][ 8 + lch4][lt8 * 4] = ng2;
        *(float4*)&gt[wid][12 + lch4][lt8 * 4] = ng3;
        *(float4*)&gt[wid][16 + lch4][lt8 * 4] = ng4;
        *(float4*)&gt[wid][20 + lch4][lt8 * 4] = ng5;
        *(float4*)&gt[wid][24 + lch4][lt8 * 4] = ng6;
        *(float4*)&gt[wid][28 + lch4][lt8 * 4] = ng7;
        __syncwarp();

        if (tile + 1 < K1NT) { K1_LDALL((tile + 1) * 8) }

        // 32 steps for chain = lane; quantize with 1-way error feedback
        unsigned uq0 = 0, uq1 = 0;
        #pragma unroll
        for (int j = 0; j < 8; j++) {
            float4 gv = *(const float4*)&gt[wid][lane][4 * j];
            __half q0, q1, q2, q3;
            float t, r, acc;

            t = gv.x + e; q0 = __float2half_rn(t); r = __half2float(q0); e = t - r;
            acc = fmaf(nki, pos, r); vs = fmaf(vs, DAMP, acc); pos = fmaf(vs, DAMP, pos);
            t = gv.y + e; q1 = __float2half_rn(t); r = __half2float(q1); e = t - r;
            acc = fmaf(nki, pos, r); vs = fmaf(vs, DAMP, acc); pos = fmaf(vs, DAMP, pos);
            t = gv.z + e; q2 = __float2half_rn(t); r = __half2float(q2); e = t - r;
            acc = fmaf(nki, pos, r); vs = fmaf(vs, DAMP, acc); pos = fmaf(vs, DAMP, pos);
            t = gv.w + e; q3 = __float2half_rn(t); r = __half2float(q3); e = t - r;
            acc = fmaf(nki, pos, r); vs = fmaf(vs, DAMP, acc); pos = fmaf(vs, DAMP, pos);

            unsigned ua = half2_as_u32(__halves2half2(q0, q1));  // q0 low
            unsigned ub = half2_as_u32(__halves2half2(q2, q3));
            if ((j & 1) == 0) { uq0 = ua; uq1 = ub; }
            else {
                uint4 pk; pk.x = uq0; pk.y = uq1; pk.z = ua; pk.w = ub;
                __stcs(gw + (size_t)(tile * 4 + (j >> 1)) * 64, pk);
            }
        }
    }
#undef K1_LDALL
#undef K1_G4

    float* fin = g_fin + ((size_t)(bm * NCH + chunk) * 64 + d) * 2;
    fin[0] = pos; fin[1] = vs;
}

// ---------------- K2: combine (inline homogeneous + chunk ICs) ----------------
__global__ __launch_bounds__(256)
void k2_combine(const float* __restrict__ masses, const float* __restrict__ tensions)
{
    int idx = blockIdx.x * 256 + threadIdx.x;      // bm*64+d
    int bm = idx >> 6, d = idx & 63, m = bm & 63;
    const float nki = -(tensions[m * 64 + d] / masses[m]);

    float p1 = 1.f, v1 = 0.f, p2 = 0.f, v2 = 1.f;
    #pragma unroll 8
    for (int t = 0; t < CL; t++) {
        v1 = fmaf(v1, DAMP, nki * p1); p1 = fmaf(v1, DAMP, p1);
        v2 = fmaf(v2, DAMP, nki * p2); p2 = fmaf(v2, DAMP, p2);
    }

    float pos = 0.f, vs = 0.f;
    #pragma unroll
    for (int c = 0; c < NCH; c++) {
        size_t o = ((size_t)(bm * NCH + c) * 64 + d) * 2;
        g_ic[o] = pos; g_ic[o + 1] = vs;
        float np = fmaf(p1, pos, fmaf(p2, vs, g_fin[o]));
        float nv = fmaf(v1, pos, fmaf(v2, vs, g_fin[o + 1]));
        pos = np; vs = nv;
    }
}

// ---------------- K3: pass B — one warp per (bm,chunk), 2 chains per lane ----
__global__ __launch_bounds__(256)
void k3_passB(const float* __restrict__ mic, const float* __restrict__ masses,
              const float* __restrict__ tensions, float* __restrict__ out)
{
    __shared__ float tile_s[8][16][36];

    const int tid = threadIdx.x, wid = tid >> 5, lane = tid & 31;
    const int unit  = blockIdx.x * 8 + wid;        // 0..2047
    const int bm    = unit >> 4;
    const int chunk = unit & 15;
    const int m = bm & 63;
    const int d0 = lane, d1 = lane + 32;

    const float inv_mass = 1.f / masses[m];
    const float nki0 = -(tensions[m * 64 + d0] * inv_mass);
    const float nki1 = -(tensions[m * 64 + d1] * inv_mass);
    const float micv0 = mic[bm * 64 + d0];
    const float micv1 = mic[bm * 64 + d1];

    const uint4* gw0 = g_scr + ((size_t)(bm * NCH + chunk) * NW8) * 64 + d0;
    const uint4* gw1 = gw0 + 32;
    const size_t ib = ((size_t)(bm * NCH + chunk) * 64) * 2;
    float pos0 = g_ic[ib + 2 * d0], vs0 = g_ic[ib + 2 * d0 + 1];
    float pos1 = g_ic[ib + 2 * d1], vs1 = g_ic[ib + 2 * d1 + 1];
    float* obase = out + (size_t)bm * TTX + (size_t)chunk * CL;
    float (*tile)[36] = tile_s[wid];

    uint4 ca00, ca01, ca10, ca11, cb00, cb01, cb10, cb11;
    ca00 = __ldcs(gw0 + 0);  ca01 = __ldcs(gw0 + 64);
    ca10 = __ldcs(gw1 + 0);  ca11 = __ldcs(gw1 + 64);

    const int NWND = CL / 16;                      // 32 windows of 16 steps

    // one uint4 pair (8 steps for both chains) starting at tile row R
#define K3_QQ(G0, G1, R)                                                       \
    _Pragma("unroll")                                                          \
    for (int i = 0; i < 4; i++) {                                              \
        float2 fa = __half22float2(u32_as_half2((&G0.x)[i]));                  \
        float2 fb = __half22float2(u32_as_half2((&G1.x)[i]));                  \
        _Pragma("unroll")                                                      \
        for (int s = 0; s < 2; s++) {                                          \
            float gv0 = s ? fa.y : fa.x;                                       \
            float gv1 = s ? fb.y : fb.x;                                       \
            float a0 = fmaf(nki0, pos0, gv0);                                  \
            vs0  = fmaf(vs0, DAMP, a0);                                        \
            pos0 = fmaf(vs0, DAMP, pos0);                                      \
            float a1 = fmaf(nki1, pos1, gv1);                                  \
            vs1  = fmaf(vs1, DAMP, a1);                                        \
            pos1 = fmaf(vs1, DAMP, pos1);                                      \
            float t0 = tanh_fast(vs0);                                         \
            float t1 = tanh_fast(vs1);                                         \
            tile[(R) + i * 2 + s][lane] = fmaf(t0, micv0, t1 * micv1);         \
        }                                                                      \
    }

#define K3W(W, C00, C01, C10, C11, N00, N01, N10, N11)                         \
    {                                                                          \
        const int w_ = (W);                                                    \
        if (w_ + 1 < NWND) {                                                   \
            N00 = __ldcs(gw0 + (size_t)(2 * (w_ + 1) + 0) * 64);               \
            N01 = __ldcs(gw0 + (size_t)(2 * (w_ + 1) + 1) * 64);               \
            N10 = __ldcs(gw1 + (size_t)(2 * (w_ + 1) + 0) * 64);               \
            N11 = __ldcs(gw1 + (size_t)(2 * (w_ + 1) + 1) * 64);               \
        }                                                                      \
        K3_QQ(C00, C10, 0)                                                     \
        K3_QQ(C01, C11, 8)                                                     \
        __syncwarp();                                                          \
        const int row = lane & 15, cb = (lane >> 4) * 16;                      \
        float s0 = 0.f, s1 = 0.f, s2 = 0.f, s3 = 0.f;                          \
        _Pragma("unroll")                                                      \
        for (int i = 0; i < 4; i++) {                                          \
            float4 v = *(const float4*)&tile[row][cb + 4 * i];                 \
            s0 += v.x; s1 += v.y; s2 += v.z; s3 += v.w;                        \
        }                                                                      \
        float sum = (s0 + s1) + (s2 + s3);                                     \
        sum += __shfl_down_sync(0xffffffffu, sum, 16);                         \
        if (lane < 16) obase[w_ * 16 + lane] = sum;                            \
        __syncwarp();                                                          \
    }

    for (int w = 0; w < NWND; w += 2) {
        K3W(w,     ca00, ca01, ca10, ca11, cb00, cb01, cb10, cb11)
        K3W(w + 1, cb00, cb01, cb10, cb11, ca00, ca01, ca10, ca11)
    }
#undef K3W
#undef K3_QQ
}

extern "C" void kernel_launch(void* const* d_in, const int* in_sizes, int n_in,
                              void* d_out, int out_size)
{
    const float* forces   = (const float*)d_in[0];
    const float* home     = (const float*)d_in[1];
    const float* mic      = (const float*)d_in[2];
    const float* masses   = (const float*)d_in[3];
    const float* tensions = (const float*)d_in[4];
    const float* gains    = (const float*)d_in[5];

    k1_passA  <<<1024, 128>>>(forces, home, masses, tensions, gains);
    k2_combine<<<32,   256>>>(masses, tensions);
    k3_passB  <<<256,  256>>>(mic, masses, tensions, (float*)d_out);
}

// round 14
// speedup vs baseline: 1.1677x; 1.0241x over previous
#include <cuda_runtime.h>
#include <cuda_fp16.h>
#include <string.h>

// GooLayer: B=2, M=64, D=64, T=8192 — chunked linear-scan, 3 kernels:
//  K1: pass A — stores g' = (f+ki*h)*(gain*DAMP) as fp16 (1-way noise-shaped
//      rounding); stages only g' (computed at load) through smem; chunk finals.
//      g stores evict-NORMAL so K3 finds them in L2. f/h reads evict-first.
//  K2: combine — inline homogeneous M^512 + 16 2x2 matvecs -> chunk ICs
//  K3: pass B — one warp per (bm,chunk), all 64 d (2 chains/lane);
//      tanh via MUFU.TANH on the scaled state; out via streaming stores.

#define BBX 2
#define MMX 64
#define DDX 64
#define TTX 8192
#define DAMP 0.9998f
#define NCH 16
#define CL (TTX / NCH)                  // 512
#define NW8 (CL / 8)                    // 64 fp16-octet windows per chunk
#define K1NT (CL / 32)                  // 16 staging tiles per chunk
#define FQ (TTX / 4)                    // float4 per chain (2048)

// g scratch: [bm][chunk][w8][d] -> uint4 (8 fp16, t-ascending), coalesced in d
__device__ uint4 g_scr[(size_t)BBX * MMX * NCH * NW8 * DDX];
__device__ float g_fin[BBX * MMX * NCH * DDX * 2];
__device__ float g_ic [BBX * MMX * NCH * DDX * 2];

__device__ __forceinline__ float tanh_fast(float x) {
    float y; asm("tanh.approx.f32 %0, %1;" : "=f"(y) : "f"(x)); return y;
}
__device__ __forceinline__ __half2 u32_as_half2(unsigned u) {
    __half2 h; memcpy(&h, &u, 4); return h;
}
__device__ __forceinline__ unsigned half2_as_u32(__half2 h) {
    unsigned u; memcpy(&u, &h, 4); return u;
}

// ---------------- K1: pass A ----------------
// 128 threads = 4 warps; one warp per (bm, chunk, half) unit. 1024 blocks.
__global__ __launch_bounds__(128)
void k1_passA(const float* __restrict__ forces, const float* __restrict__ home,
              const float* __restrict__ masses, const float* __restrict__ tensions,
              const float* __restrict__ gains)
{
    __shared__ float gt[4][32][36];   // staged g' tiles: [warp][chain][t]
    __shared__ float kis[4][32];      // per-chain ki

    const int tid = threadIdx.x, wid = tid >> 5, lane = tid & 31;
    const int unit  = blockIdx.x * 4 + wid;        // 0..4095
    const int bm    = unit >> 5;
    const int chunk = (unit >> 1) & 15;
    const int half  = unit & 1;
    const int m = bm & 63;
    const int d = half * 32 + lane;

    const float ki   = tensions[m * 64 + d] / masses[m];
    const float nki  = -ki;
    const float karg = gains[m] * DAMP;            // state scale (tanh arg)

    kis[wid][lane] = ki;
    __syncwarp();

    // per LDG.128: lanes cover 4 chains x 8 float4 (full 128B lines)
    const int lch4 = lane >> 3;                    // 0..3
    const int lt8  = lane & 7;                     // 0..7
    const size_t wb = ((size_t)(bm * 64 + half * 32)) * TTX + (size_t)chunk * CL;
    const float4* __restrict__ fbase = (const float4*)(forces + wb) + lt8;
    const float4* __restrict__ hbase = (const float4*)(home  + wb) + lt8;

    float kk0 = kis[wid][ 0 + lch4], kk1 = kis[wid][ 4 + lch4];
    float kk2 = kis[wid][ 8 + lch4], kk3 = kis[wid][12 + lch4];
    float kk4 = kis[wid][16 + lch4], kk5 = kis[wid][20 + lch4];
    float kk6 = kis[wid][24 + lch4], kk7 = kis[wid][28 + lch4];

    uint4* gw = g_scr + ((size_t)(bm * NCH + chunk) * NW8) * 64 + d;

    float pos = 0.f, vs = 0.f, e = 0.f;            // karg-scaled state

    float4 nf0, nf1, nf2, nf3, nf4, nf5, nf6, nf7;
    float4 nh0, nh1, nh2, nh3, nh4, nh5, nh6, nh7;

#define K1_LDALL(OFF)                                                          \
    nf0 = __ldcs(fbase + (size_t)(0 * 4 + lch4) * FQ + (OFF));                 \
    nf1 = __ldcs(fbase + (size_t)(1 * 4 + lch4) * FQ + (OFF));                 \
    nf2 = __ldcs(fbase + (size_t)(2 * 4 + lch4) * FQ + (OFF));                 \
    nf3 = __ldcs(fbase + (size_t)(3 * 4 + lch4) * FQ + (OFF));                 \
    nf4 = __ldcs(fbase + (size_t)(4 * 4 + lch4) * FQ + (OFF));                 \
    nf5 = __ldcs(fbase + (size_t)(5 * 4 + lch4) * FQ + (OFF));                 \
    nf6 = __ldcs(fbase + (size_t)(6 * 4 + lch4) * FQ + (OFF));                 \
    nf7 = __ldcs(fbase + (size_t)(7 * 4 + lch4) * FQ + (OFF));                 \
    nh0 = __ldcs(hbase + (size_t)(0 * 4 + lch4) * FQ + (OFF));                 \
    nh1 = __ldcs(hbase + (size_t)(1 * 4 + lch4) * FQ + (OFF));                 \
    nh2 = __ldcs(hbase + (size_t)(2 * 4 + lch4) * FQ + (OFF));                 \
    nh3 = __ldcs(hbase + (size_t)(3 * 4 + lch4) * FQ + (OFF));                 \
    nh4 = __ldcs(hbase + (size_t)(4 * 4 + lch4) * FQ + (OFF));                 \
    nh5 = __ldcs(hbase + (size_t)(5 * 4 + lch4) * FQ + (OFF));                 \
    nh6 = __ldcs(hbase + (size_t)(6 * 4 + lch4) * FQ + (OFF));                 \
    nh7 = __ldcs(hbase + (size_t)(7 * 4 + lch4) * FQ + (OFF));

#define K1_G4(NF, NH, KK)                                                      \
    make_float4(fmaf(KK, NH.x, NF.x) * karg, fmaf(KK, NH.y, NF.y) * karg,      \
                fmaf(KK, NH.z, NF.z) * karg, fmaf(KK, NH.w, NF.w) * karg)

    K1_LDALL(0)

    for (int tile = 0; tile < K1NT; tile++) {
        float4 ng0 = K1_G4(nf0, nh0, kk0), ng1 = K1_G4(nf1, nh1, kk1);
        float4 ng2 = K1_G4(nf2, nh2, kk2), ng3 = K1_G4(nf3, nh3, kk3);
        float4 ng4 = K1_G4(nf4, nh4, kk4), ng5 = K1_G4(nf5, nh5, kk5);
        float4 ng6 = K1_G4(nf6, nh6, kk6), ng7 = K1_G4(nf7, nh7, kk7);

        __syncwarp();
        *(float4*)&gt[wid][ 0 + lch4][lt8 * 4] = ng0;
        *(float4*)&gt[wid][ 4 + lch4][lt8 * 4] = ng1;
        *(float4*)&gt[wid][ 8 + lch4][lt8 * 4] = ng2;
        *(float4*)&gt[wid][12 + lch4][lt8 * 4] = ng3;
        *(float4*)&gt[wid][16 + lch4][lt8 * 4] = ng4;
        *(float4*)&gt[wid][20 + lch4][lt8 * 4] = ng5;
        *(float4*)&gt[wid][24 + lch4][lt8 * 4] = ng6;
        *(float4*)&gt[wid][28 + lch4][lt8 * 4] = ng7;
        __syncwarp();

        if (tile + 1 < K1NT) { K1_LDALL((tile + 1) * 8) }

        // 32 steps for chain = lane; quantize with 1-way error feedback
        unsigned uq0 = 0, uq1 = 0;
        #pragma unroll
        for (int j = 0; j < 8; j++) {
            float4 gv = *(const float4*)&gt[wid][lane][4 * j];
            __half q0, q1, q2, q3;
            float t, r, acc;

            t = gv.x + e; q0 = __float2half_rn(t); r = __half2float(q0); e = t - r;
            acc = fmaf(nki, pos, r); vs = fmaf(vs, DAMP, acc); pos = fmaf(vs, DAMP, pos);
            t = gv.y + e; q1 = __float2half_rn(t); r = __half2float(q1); e = t - r;
            acc = fmaf(nki, pos, r); vs = fmaf(vs, DAMP, acc); pos = fmaf(vs, DAMP, pos);
            t = gv.z + e; q2 = __float2half_rn(t); r = __half2float(q2); e = t - r;
            acc = fmaf(nki, pos, r); vs = fmaf(vs, DAMP, acc); pos = fmaf(vs, DAMP, pos);
            t = gv.w + e; q3 = __float2half_rn(t); r = __half2float(q3); e = t - r;
            acc = fmaf(nki, pos, r); vs = fmaf(vs, DAMP, acc); pos = fmaf(vs, DAMP, pos);

            unsigned ua = half2_as_u32(__halves2half2(q0, q1));  // q0 low
            unsigned ub = half2_as_u32(__halves2half2(q2, q3));
            if ((j & 1) == 0) { uq0 = ua; uq1 = ub; }
            else {
                uint4 pk; pk.x = uq0; pk.y = uq1; pk.z = ua; pk.w = ub;
                // evict-normal store: keep g resident in L2 for K3
                gw[(size_t)(tile * 4 + (j >> 1)) * 64] = pk;
            }
        }
    }
#undef K1_LDALL
#undef K1_G4

    float* fin = g_fin + ((size_t)(bm * NCH + chunk) * 64 + d) * 2;
    fin[0] = pos; fin[1] = vs;
}

// ---------------- K2: combine (inline homogeneous + chunk ICs) ----------------
__global__ __launch_bounds__(256)
void k2_combine(const float* __restrict__ masses, const float* __restrict__ tensions)
{
    int idx = blockIdx.x * 256 + threadIdx.x;      // bm*64+d
    int bm = idx >> 6, d = idx & 63, m = bm & 63;
    const float nki = -(tensions[m * 64 + d] / masses[m]);

    float p1 = 1.f, v1 = 0.f, p2 = 0.f, v2 = 1.f;
    #pragma unroll 8
    for (int t = 0; t < CL; t++) {
        v1 = fmaf(v1, DAMP, nki * p1); p1 = fmaf(v1, DAMP, p1);
        v2 = fmaf(v2, DAMP, nki * p2); p2 = fmaf(v2, DAMP, p2);
    }

    float pos = 0.f, vs = 0.f;
    #pragma unroll
    for (int c = 0; c < NCH; c++) {
        size_t o = ((size_t)(bm * NCH + c) * 64 + d) * 2;
        g_ic[o] = pos; g_ic[o + 1] = vs;
        float np = fmaf(p1, pos, fmaf(p2, vs, g_fin[o]));
        float nv = fmaf(v1, pos, fmaf(v2, vs, g_fin[o + 1]));
        pos = np; vs = nv;
    }
}

// ---------------- K3: pass B — one warp per (bm,chunk), 2 chains per lane ----
// 128 threads = 4 warps per block, 512 blocks (better SM load balance).
__global__ __launch_bounds__(128)
void k3_passB(const float* __restrict__ mic, const float* __restrict__ masses,
              const float* __restrict__ tensions, float* __restrict__ out)
{
    __shared__ float tile_s[4][16][36];

    const int tid = threadIdx.x, wid = tid >> 5, lane = tid & 31;
    const int unit  = blockIdx.x * 4 + wid;        // 0..2047
    const int bm    = unit >> 4;
    const int chunk = unit & 15;
    const int m = bm & 63;
    const int d0 = lane, d1 = lane + 32;

    const float inv_mass = 1.f / masses[m];
    const float nki0 = -(tensions[m * 64 + d0] * inv_mass);
    const float nki1 = -(tensions[m * 64 + d1] * inv_mass);
    const float micv0 = mic[bm * 64 + d0];
    const float micv1 = mic[bm * 64 + d1];

    const uint4* gw0 = g_scr + ((size_t)(bm * NCH + chunk) * NW8) * 64 + d0;
    const uint4* gw1 = gw0 + 32;
    const size_t ib = ((size_t)(bm * NCH + chunk) * 64) * 2;
    float pos0 = g_ic[ib + 2 * d0], vs0 = g_ic[ib + 2 * d0 + 1];
    float pos1 = g_ic[ib + 2 * d1], vs1 = g_ic[ib + 2 * d1 + 1];
    float* obase = out + (size_t)bm * TTX + (size_t)chunk * CL;
    float (*tile)[36] = tile_s[wid];

    uint4 ca00, ca01, ca10, ca11, cb00, cb01, cb10, cb11;
    ca00 = gw0[0];  ca01 = gw0[64];   // default policy: L2 hits from K1
    ca10 = gw1[0];  ca11 = gw1[64];

    const int NWND = CL / 16;                      // 32 windows of 16 steps

    // one uint4 pair (8 steps for both chains) starting at tile row R
#define K3_QQ(G0, G1, R)                                                       \
    _Pragma("unroll")                                                          \
    for (int i = 0; i < 4; i++) {                                              \
        float2 fa = __half22float2(u32_as_half2((&G0.x)[i]));                  \
        float2 fb = __half22float2(u32_as_half2((&G1.x)[i]));                  \
        _Pragma("unroll")                                                      \
        for (int s = 0; s < 2; s++) {                                          \
            float gv0 = s ? fa.y : fa.x;                                       \
            float gv1 = s ? fb.y : fb.x;                                       \
            float a0 = fmaf(nki0, pos0, gv0);                                  \
            vs0  = fmaf(vs0, DAMP, a0);                                        \
            pos0 = fmaf(vs0, DAMP, pos0);                                      \
            float a1 = fmaf(nki1, pos1, gv1);                                  \
            vs1  = fmaf(vs1, DAMP, a1);                                        \
            pos1 = fmaf(vs1, DAMP, pos1);                                      \
            float t0 = tanh_fast(vs0);                                         \
            float t1 = tanh_fast(vs1);                                         \
            tile[(R) + i * 2 + s][lane] = fmaf(t0, micv0, t1 * micv1);         \
        }                                                                      \
    }

#define K3W(W, C00, C01, C10, C11, N00, N01, N10, N11)                         \
    {                                                                          \
        const int w_ = (W);                                                    \
        if (w_ + 1 < NWND) {                                                   \
            N00 = gw0[(size_t)(2 * (w_ + 1) + 0) * 64];                        \
            N01 = gw0[(size_t)(2 * (w_ + 1) + 1) * 64];                        \
            N10 = gw1[(size_t)(2 * (w_ + 1) + 0) * 64];                        \
            N11 = gw1[(size_t)(2 * (w_ + 1) + 1) * 64];                        \
        }                                                                      \
        K3_QQ(C00, C10, 0)                                                     \
        K3_QQ(C01, C11, 8)                                                     \
        __syncwarp();                                                          \
        const int row = lane & 15, cb = (lane >> 4) * 16;                      \
        float s0 = 0.f, s1 = 0.f, s2 = 0.f, s3 = 0.f;                          \
        _Pragma("unroll")                                                      \
        for (int i = 0; i < 4; i++) {                                          \
            float4 v = *(const float4*)&tile[row][cb + 4 * i];                 \
            s0 += v.x; s1 += v.y; s2 += v.z; s3 += v.w;                        \
        }                                                                      \
        float sum = (s0 + s1) + (s2 + s3);                                     \
        sum += __shfl_down_sync(0xffffffffu, sum, 16);                         \
        if (lane < 16) __stcs(obase + w_ * 16 + lane, sum);                    \
        __syncwarp();                                                          \
    }

    for (int w = 0; w < NWND; w += 2) {
        K3W(w,     ca00, ca01, ca10, ca11, cb00, cb01, cb10, cb11)
        K3W(w + 1, cb00, cb01, cb10, cb11, ca00, ca01, ca10, ca11)
    }
#undef K3W
#undef K3_QQ
}

extern "C" void kernel_launch(void* const* d_in, const int* in_sizes, int n_in,
                              void* d_out, int out_size)
{
    const float* forces   = (const float*)d_in[0];
    const float* home     = (const float*)d_in[1];
    const float* mic      = (const float*)d_in[2];
    const float* masses   = (const float*)d_in[3];
    const float* tensions = (const float*)d_in[4];
    const float* gains    = (const float*)d_in[5];

    k1_passA  <<<1024, 128>>>(forces, home, masses, tensions, gains);
    k2_combine<<<32,   256>>>(masses, tensions);
    k3_passB  <<<512,  128>>>(mic, masses, tensions, (float*)d_out);
}